// round 10
// baseline (speedup 1.0000x reference)
#include <cuda_runtime.h>
#include <cstdint>

#define BATCH 32
#define NPTS  2048
#define DIM   16
#define TN    64
#define TM    128
#define NTHR  128
#define GRIDX 13             // 13*32 = 416 blocks = one wave at 3 CTAs/SM
#define NTILE (NPTS / TN)
#define ASTR  72             // A transposed row stride (floats)
#define BSTR  144            // B transposed row stride (floats), gapped
#define BIG2  1.0e16f
#define HUGEV 1.0e30f

typedef unsigned long long ull;

// physical column for Bs_t: 4-float gap every 32 columns (bank de-conflict)
__device__ __forceinline__ int bpcol(int col) { return col + ((col >> 5) << 2); }

// ---------------- scratch (no allocs allowed) ----------------
__device__ float g_cA[BATCH * NPTS * DIM];   // holds -2 * outputs (valid, packed)
__device__ float g_cB[BATCH * NPTS * DIM];
__device__ float g_wA[BATCH * NPTS];
__device__ float g_wB[BATCH * NPTS];
__device__ int   g_cntA[BATCH];
__device__ int   g_cntB[BATCH];
__device__ int   g_colmin[BATCH * NPTS];   // float-as-int (nonneg), +inf init
__device__ int   g_done[BATCH];

// ---------------- packed f32x2 helpers ----------------
__device__ __forceinline__ void fma2(ull& d, ull a, ull b) {
    asm("fma.rn.f32x2 %0, %1, %2, %0;" : "+l"(d) : "l"(a), "l"(b));
}
__device__ __forceinline__ ull add2(ull a, ull b) {
    ull d; asm("add.rn.f32x2 %0, %1, %2;" : "=l"(d) : "l"(a), "l"(b));
    return d;
}
__device__ __forceinline__ ull bcast2(float x) {
    ull d; asm("mov.b64 %0, {%1, %1};" : "=l"(d) : "f"(x));
    return d;
}
__device__ __forceinline__ void unpack2(ull v, float& lo, float& hi) {
    asm("mov.b64 {%0, %1}, %2;" : "=f"(lo), "=f"(hi) : "l"(v));
}

// ---------------- setup: init + prefix-scan compaction ----------------
__global__ __launch_bounds__(256) void setup_kernel(
    const float* __restrict__ ow, const float* __restrict__ op,
    const float* __restrict__ tw, const float* __restrict__ tp,
    float* out) {
    int blk = blockIdx.x;              // 64 blocks: (b, sel)
    int b   = blk >> 1;
    int sel = blk & 1;
    int tid = threadIdx.x, lane = tid & 31, wrp = tid >> 5;

    int base = blk * 1024;
    for (int i = tid; i < 1024; i += 256) g_colmin[base + i] = 0x7F800000;
    if (sel == 0 && tid == 0) { out[b] = 0.0f; g_done[b] = 0; }

    const float* w   = sel ? tw : ow;
    const float* pts = sel ? tp : op;
    float* dstP = sel ? g_cB : g_cA;
    float* dstW = sel ? g_wB : g_wA;
    int*   cnt  = sel ? g_cntB : g_cntA;
    float  scale = sel ? 1.0f : -2.0f;   // A side pre-scaled by -2

    int i0 = tid * 8;
    float wv[8];
    int c = 0;
    #pragma unroll
    for (int k = 0; k < 8; k++) {
        wv[k] = w[b * NPTS + i0 + k];
        c += (wv[k] != 0.0f);
    }
    int incl = c;
    #pragma unroll
    for (int d = 1; d < 32; d <<= 1) {
        int n = __shfl_up_sync(0xFFFFFFFFu, incl, d);
        if (lane >= d) incl += n;
    }
    __shared__ int wtot[8], wbase[8];
    if (lane == 31) wtot[wrp] = incl;
    __syncthreads();
    if (tid == 0) {
        int s = 0;
        #pragma unroll
        for (int wI = 0; wI < 8; wI++) { wbase[wI] = s; s += wtot[wI]; }
        cnt[b] = s;
    }
    __syncthreads();
    int p = wbase[wrp] + incl - c;
    #pragma unroll
    for (int k = 0; k < 8; k++) {
        if (wv[k] != 0.0f) {
            const float4* s4 = (const float4*)(pts + ((size_t)b * NPTS + i0 + k) * DIM);
            float4* d4 = (float4*)(dstP + ((size_t)b * NPTS + p) * DIM);
            #pragma unroll
            for (int q = 0; q < 4; q++) {
                float4 v = s4[q];
                v.x *= scale; v.y *= scale; v.z *= scale; v.w *= scale;
                d4[q] = v;
            }
            dstW[b * NPTS + p] = wv[k];
            p++;
        }
    }
}

// -- pair kernel: 64x128 tile, dbl-buffered B, pipelined frags, 170 regs ----
__global__ __launch_bounds__(NTHR, 3) void pair_kernel(float* out) {
    int b  = blockIdx.y;
    int Nv = g_cntA[b];
    int Mv = g_cntB[b];
    int bx = blockIdx.x;

    __shared__ __align__(16) float As_t[16 * ASTR];
    __shared__ __align__(16) float Bs_t[2][16 * BSTR];
    __shared__ __align__(16) float asq[TN];
    __shared__ __align__(16) float bsq[2][TM];
    __shared__ float csh[2][4 * TM];
    __shared__ int   s_last;

    int tid  = threadIdx.x;
    int tx   = tid & 15;     // col group: cols tx*8 + c
    int ty   = tid >> 4;     // row group: rows ty*8 + r
    int lane = tid & 31;
    int wrp  = tid >> 5;
    int bro  = bpcol(tx * 8);
    int myc  = bpcol(tid);   // this thread's owned B column (physical)
    int mtiles = (Mv + TM - 1) / TM;

    for (int t = bx; t < NTILE; t += GRIDX) {
        int n0 = t * TN;
        if (n0 >= Nv) break;

        __syncthreads();   // protect As_t/asq/csh reuse across t-iterations

        // ---- load A tile (64 rows x 16 of -2*a), k-transposed; asq=0.25*Σv² --
        {
            int row = tid >> 1, half = tid & 1;
            int g = n0 + row;
            float4 v0 = make_float4(0.f, 0.f, 0.f, 0.f), v1 = v0;
            if (g < Nv) {
                const float4* p4 = (const float4*)(g_cA + ((size_t)b * NPTS + g) * DIM);
                v0 = p4[2 * half]; v1 = p4[2 * half + 1];
            }
            int k0 = 8 * half;
            As_t[(k0 + 0) * ASTR + row] = v0.x;
            As_t[(k0 + 1) * ASTR + row] = v0.y;
            As_t[(k0 + 2) * ASTR + row] = v0.z;
            As_t[(k0 + 3) * ASTR + row] = v0.w;
            As_t[(k0 + 4) * ASTR + row] = v1.x;
            As_t[(k0 + 5) * ASTR + row] = v1.y;
            As_t[(k0 + 6) * ASTR + row] = v1.z;
            As_t[(k0 + 7) * ASTR + row] = v1.w;
            float p = v0.x * v0.x + v0.y * v0.y + v0.z * v0.z + v0.w * v0.w
                    + v1.x * v1.x + v1.y * v1.y + v1.z * v1.z + v1.w * v1.w;
            p += __shfl_xor_sync(0xFFFFFFFFu, p, 1);
            if (half == 0) asq[row] = (g < Nv) ? (0.25f * p) : HUGEV;
        }

        float rowmin[8];
        #pragma unroll
        for (int r = 0; r < 8; r++) rowmin[r] = HUGEV;

        // ---- load + STS B(0) into buffer 0 ----
        {
            float4 nb0, nb1, nb2, nb3;
            float4 z = make_float4(0.f, 0.f, 0.f, 0.f);
            nb0 = nb1 = nb2 = nb3 = z;
            if (tid < Mv) {
                const float4* p4 = (const float4*)(g_cB + ((size_t)b * NPTS + tid) * DIM);
                nb0 = p4[0]; nb1 = p4[1]; nb2 = p4[2]; nb3 = p4[3];
            }
            float* B0 = Bs_t[0];
            B0[ 0 * BSTR + myc] = nb0.x;  B0[ 1 * BSTR + myc] = nb0.y;
            B0[ 2 * BSTR + myc] = nb0.z;  B0[ 3 * BSTR + myc] = nb0.w;
            B0[ 4 * BSTR + myc] = nb1.x;  B0[ 5 * BSTR + myc] = nb1.y;
            B0[ 6 * BSTR + myc] = nb1.z;  B0[ 7 * BSTR + myc] = nb1.w;
            B0[ 8 * BSTR + myc] = nb2.x;  B0[ 9 * BSTR + myc] = nb2.y;
            B0[10 * BSTR + myc] = nb2.z;  B0[11 * BSTR + myc] = nb2.w;
            B0[12 * BSTR + myc] = nb3.x;  B0[13 * BSTR + myc] = nb3.y;
            B0[14 * BSTR + myc] = nb3.z;  B0[15 * BSTR + myc] = nb3.w;
            float p = nb0.x*nb0.x + nb0.y*nb0.y + nb0.z*nb0.z + nb0.w*nb0.w
                    + nb1.x*nb1.x + nb1.y*nb1.y + nb1.z*nb1.z + nb1.w*nb1.w
                    + nb2.x*nb2.x + nb2.y*nb2.y + nb2.z*nb2.z + nb2.w*nb2.w
                    + nb3.x*nb3.x + nb3.y*nb3.y + nb3.z*nb3.z + nb3.w*nb3.w;
            bsq[0][tid] = (tid < Mv) ? p : HUGEV;
        }
        __syncthreads();   // A + B(0) visible

        // aq2 constant across m-tiles
        ulonglong2 q0 = *(const ulonglong2*)(asq + ty * 8);
        ulonglong2 q1 = *(const ulonglong2*)(asq + ty * 8 + 4);
        ull aq2[4] = {q0.x, q0.y, q1.x, q1.y};

        for (int mt = 0; mt < mtiles; mt++) {
            int m0 = mt * TM;
            int par = mt & 1;
            const float* Bcur = Bs_t[par];

            // ---- prefetch B(mt+1) into registers (LDG, long latency) ----
            float4 nb0, nb1, nb2, nb3;
            {
                float4 z = make_float4(0.f, 0.f, 0.f, 0.f);
                nb0 = nb1 = nb2 = nb3 = z;
                int g = m0 + TM + tid;
                if (mt + 1 < mtiles && g < Mv) {
                    const float4* p4 = (const float4*)(g_cB + ((size_t)b * NPTS + g) * DIM);
                    nb0 = p4[0]; nb1 = p4[1]; nb2 = p4[2]; nb3 = p4[3];
                }
            }

            // ---- mainloop: acc[p][c] init = asq(rows), += (-2a)·b ----
            ull acc[4][8];
            #pragma unroll
            for (int p = 0; p < 4; p++)
                #pragma unroll
                for (int c = 0; c < 8; c++) acc[p][c] = aq2[p];

            // software-pipelined fragments: load k+1 while computing k
            ulonglong2 A0c = *(const ulonglong2*)(As_t + ty * 8);
            ulonglong2 A1c = *(const ulonglong2*)(As_t + ty * 8 + 4);
            float4 B0c = *(const float4*)(Bcur + bro);
            float4 B1c = *(const float4*)(Bcur + bro + 4);
            #pragma unroll
            for (int k = 0; k < 16; k++) {
                ulonglong2 A0n, A1n; float4 B0n, B1n;
                if (k < 15) {
                    const float* arow = As_t + (k + 1) * ASTR + ty * 8;
                    A0n = *(const ulonglong2*)(arow);
                    A1n = *(const ulonglong2*)(arow + 4);
                    const float* brow = Bcur + (k + 1) * BSTR + bro;
                    B0n = *(const float4*)(brow);
                    B1n = *(const float4*)(brow + 4);
                }
                ull a2[4] = {A0c.x, A0c.y, A1c.x, A1c.y};
                float bs[8] = {B0c.x, B0c.y, B0c.z, B0c.w,
                               B1c.x, B1c.y, B1c.z, B1c.w};
                #pragma unroll
                for (int c = 0; c < 8; c++) {
                    ull bb = bcast2(bs[c]);
                    #pragma unroll
                    for (int p = 0; p < 4; p++) fma2(acc[p][c], a2[p], bb);
                }
                if (k < 15) { A0c = A0n; A1c = A1n; B0c = B0n; B1c = B1n; }
            }

            // ---- epilogue: d2 = acc + bsq, mins ----
            float cm[8];
            #pragma unroll
            for (int c = 0; c < 8; c++) cm[c] = HUGEV;
            #pragma unroll
            for (int c = 0; c < 8; c++) {
                ull bb = bcast2(bsq[par][tx * 8 + c]);
                #pragma unroll
                for (int p = 0; p < 4; p++) {
                    ull d2 = add2(acc[p][c], bb);
                    float lo, hi;
                    unpack2(d2, lo, hi);
                    rowmin[2 * p]     = fminf(rowmin[2 * p], lo);
                    rowmin[2 * p + 1] = fminf(rowmin[2 * p + 1], hi);
                    cm[c] = fminf(cm[c], fminf(lo, hi));
                }
            }

            // ---- col-min: shfl merge halves, stage into csh[par] ----
            #pragma unroll
            for (int c = 0; c < 8; c++) {
                float v = fmaxf(cm[c], 0.0f);   // clamp -> int-ordered atomicMin
                v = fminf(v, __shfl_xor_sync(0xFFFFFFFFu, v, 16));
                if (lane < 16) csh[par][wrp * TM + tx * 8 + c] = v;
            }

            // ---- STS B(mt+1) into other buffer ----
            if (mt + 1 < mtiles) {
                float* Bn = Bs_t[par ^ 1];
                Bn[ 0 * BSTR + myc] = nb0.x;  Bn[ 1 * BSTR + myc] = nb0.y;
                Bn[ 2 * BSTR + myc] = nb0.z;  Bn[ 3 * BSTR + myc] = nb0.w;
                Bn[ 4 * BSTR + myc] = nb1.x;  Bn[ 5 * BSTR + myc] = nb1.y;
                Bn[ 6 * BSTR + myc] = nb1.z;  Bn[ 7 * BSTR + myc] = nb1.w;
                Bn[ 8 * BSTR + myc] = nb2.x;  Bn[ 9 * BSTR + myc] = nb2.y;
                Bn[10 * BSTR + myc] = nb2.z;  Bn[11 * BSTR + myc] = nb2.w;
                Bn[12 * BSTR + myc] = nb3.x;  Bn[13 * BSTR + myc] = nb3.y;
                Bn[14 * BSTR + myc] = nb3.z;  Bn[15 * BSTR + myc] = nb3.w;
                float p = nb0.x*nb0.x + nb0.y*nb0.y + nb0.z*nb0.z + nb0.w*nb0.w
                        + nb1.x*nb1.x + nb1.y*nb1.y + nb1.z*nb1.z + nb1.w*nb1.w
                        + nb2.x*nb2.x + nb2.y*nb2.y + nb2.z*nb2.z + nb2.w*nb2.w
                        + nb3.x*nb3.x + nb3.y*nb3.y + nb3.z*nb3.z + nb3.w*nb3.w;
                bsq[par ^ 1][tid] = (m0 + TM + tid < Mv) ? p : HUGEV;
            }
            __syncthreads();   // csh[par] + next B buffer ready

            // ---- merge csh[par] across 4 warps, one atomicMin per col ----
            {
                float v =    csh[par][0 * TM + tid];
                v = fminf(v, csh[par][1 * TM + tid]);
                v = fminf(v, csh[par][2 * TM + tid]);
                v = fminf(v, csh[par][3 * TM + tid]);
                if (m0 + tid < Mv)
                    atomicMin(&g_colmin[b * NPTS + m0 + tid], __float_as_int(v));
            }
        }

        // ---- row-min reduction over tx lanes (xor 1,2,4,8) ----
        #pragma unroll
        for (int r = 0; r < 8; r++) {
            float v = rowmin[r];
            v = fminf(v, __shfl_xor_sync(0xFFFFFFFFu, v, 1));
            v = fminf(v, __shfl_xor_sync(0xFFFFFFFFu, v, 2));
            v = fminf(v, __shfl_xor_sync(0xFFFFFFFFu, v, 4));
            v = fminf(v, __shfl_xor_sync(0xFFFFFFFFu, v, 8));
            rowmin[r] = v;
        }
        if (tx == 0) {
            float contrib = 0.0f;
            #pragma unroll
            for (int r = 0; r < 8; r++) {
                int g = n0 + ty * 8 + r;
                if (g < Nv) {
                    float rv = rowmin[r];
                    float val = (rv >= 1e29f) ? BIG2 : fmaxf(rv, 0.0f);
                    contrib += val * g_wA[b * NPTS + g];
                }
            }
            atomicAdd(&out[b], contrib);
        }
    }

    // ---- every block arrives once; last of GRIDX finalizes col mins ----
    __threadfence();
    __syncthreads();
    if (tid == 0)
        s_last = (atomicAdd(&g_done[b], 1) == GRIDX - 1) ? 1 : 0;
    __syncthreads();
    if (s_last) {
        float s = 0.0f;
        for (int m = tid; m < Mv; m += NTHR) {
            float v = __int_as_float(__ldcg(&g_colmin[b * NPTS + m]));
            v = (v >= 1e29f) ? BIG2 : v;
            s += v * g_wB[b * NPTS + m];
        }
        #pragma unroll
        for (int d = 16; d > 0; d >>= 1)
            s += __shfl_xor_sync(0xFFFFFFFFu, s, d);
        if (lane == 0) atomicAdd(&out[b], s);
    }
}

// ---------------- launch ----------------
extern "C" void kernel_launch(void* const* d_in, const int* in_sizes, int n_in,
                              void* d_out, int out_size) {
    const float* ow = (const float*)d_in[0];  // [B, N]
    const float* op = (const float*)d_in[1];  // [B, N, D]
    const float* tw = (const float*)d_in[2];  // [B, M]
    const float* tp = (const float*)d_in[3];  // [B, M, D]
    float* out = (float*)d_out;               // [B]

    setup_kernel<<<2 * BATCH, 256>>>(ow, op, tw, tp, out);
    dim3 grid(GRIDX, BATCH);
    pair_kernel<<<grid, NTHR>>>(out);
}

// round 12
// speedup vs baseline: 1.1891x; 1.1891x over previous
#include <cuda_runtime.h>
#include <cstdint>

#define BATCH 32
#define NPTS  2048
#define DIM   16
#define TN    64
#define TM    64
#define NTHR  128
#define GRIDN 14             // n-slot count; strided over NTILE
#define MSPLIT 2             // m-range halves
#define ARRIVALS (GRIDN * MSPLIT)
#define NTILE (NPTS / TN)    // 32 logical n-tiles
#define ASTR  68             // A transposed row stride (floats), 16B-aligned
#define BSTR  68             // B transposed row stride (floats), gapped cols
#define BIG2  1.0e16f
#define HUGEV 1.0e30f

typedef unsigned long long ull;

// physical column for Bs_t: 4-float gap every 32 columns (bank de-conflict)
__device__ __forceinline__ int bpcol(int col) { return col + ((col >> 5) << 2); }

// ---------------- scratch (no allocs allowed) ----------------
__device__ float g_cA[BATCH * NPTS * DIM];   // -2 * outputs (valid, packed)
__device__ float g_cB[BATCH * NPTS * DIM];
__device__ float g_wA[BATCH * NPTS];
__device__ float g_wB[BATCH * NPTS];
__device__ int   g_cntA[BATCH];
__device__ int   g_cntB[BATCH];
__device__ int   g_colmin[BATCH * NPTS];   // float-as-int (nonneg), +inf init
__device__ int   g_rowmin[BATCH * NPTS];   // float-as-int (nonneg), +inf init
__device__ int   g_done[BATCH];

// ---------------- packed f32x2 helpers ----------------
__device__ __forceinline__ void fma2(ull& d, ull a, ull b) {
    asm("fma.rn.f32x2 %0, %1, %2, %0;" : "+l"(d) : "l"(a), "l"(b));
}
__device__ __forceinline__ ull add2(ull a, ull b) {
    ull d; asm("add.rn.f32x2 %0, %1, %2;" : "=l"(d) : "l"(a), "l"(b));
    return d;
}
__device__ __forceinline__ ull bcast2(float x) {
    ull d; asm("mov.b64 %0, {%1, %1};" : "=l"(d) : "f"(x));
    return d;
}
__device__ __forceinline__ void unpack2(ull v, float& lo, float& hi) {
    asm("mov.b64 {%0, %1}, %2;" : "=f"(lo), "=f"(hi) : "l"(v));
}

// ---------------- setup: init + prefix-scan compaction ----------------
__global__ __launch_bounds__(256) void setup_kernel(
    const float* __restrict__ ow, const float* __restrict__ op,
    const float* __restrict__ tw, const float* __restrict__ tp,
    float* out) {
    int blk = blockIdx.x;              // 64 blocks: (b, sel)
    int b   = blk >> 1;
    int sel = blk & 1;
    int tid = threadIdx.x, lane = tid & 31, wrp = tid >> 5;

    int base = blk * 1024;
    for (int i = tid; i < 1024; i += 256) {
        g_colmin[base + i] = 0x7F800000;
        g_rowmin[base + i] = 0x7F800000;
    }
    if (sel == 0 && tid == 0) { out[b] = 0.0f; g_done[b] = 0; }

    const float* w   = sel ? tw : ow;
    const float* pts = sel ? tp : op;
    float* dstP = sel ? g_cB : g_cA;
    float* dstW = sel ? g_wB : g_wA;
    int*   cnt  = sel ? g_cntB : g_cntA;
    float  scale = sel ? 1.0f : -2.0f;   // A side pre-scaled by -2

    int i0 = tid * 8;
    float wv[8];
    int c = 0;
    #pragma unroll
    for (int k = 0; k < 8; k++) {
        wv[k] = w[b * NPTS + i0 + k];
        c += (wv[k] != 0.0f);
    }
    int incl = c;
    #pragma unroll
    for (int d = 1; d < 32; d <<= 1) {
        int n = __shfl_up_sync(0xFFFFFFFFu, incl, d);
        if (lane >= d) incl += n;
    }
    __shared__ int wtot[8], wbase[8];
    if (lane == 31) wtot[wrp] = incl;
    __syncthreads();
    if (tid == 0) {
        int s = 0;
        #pragma unroll
        for (int wI = 0; wI < 8; wI++) { wbase[wI] = s; s += wtot[wI]; }
        cnt[b] = s;
    }
    __syncthreads();
    int p = wbase[wrp] + incl - c;
    #pragma unroll
    for (int k = 0; k < 8; k++) {
        if (wv[k] != 0.0f) {
            const float4* s4 = (const float4*)(pts + ((size_t)b * NPTS + i0 + k) * DIM);
            float4* d4 = (float4*)(dstP + ((size_t)b * NPTS + p) * DIM);
            #pragma unroll
            for (int q = 0; q < 4; q++) {
                float4 v = s4[q];
                v.x *= scale; v.y *= scale; v.z *= scale; v.w *= scale;
                d4[q] = v;
            }
            dstW[b * NPTS + p] = wv[k];
            p++;
        }
    }
}

// ---- pair kernel: 64x64 tile, 8x4 frag, 128 thr, 6 CTAs/SM, m-split ------
__global__ __launch_bounds__(NTHR, 6) void pair_kernel(float* out) {
    int b   = blockIdx.y;
    int Nv  = g_cntA[b];
    int Mv  = g_cntB[b];
    int bxn = blockIdx.x % GRIDN;
    int mh  = blockIdx.x / GRIDN;       // 0 or 1: which m-half

    __shared__ __align__(16) float As_t[16 * ASTR];
    __shared__ __align__(16) float Bs_t[16 * BSTR];
    __shared__ __align__(16) float asq[TN];
    __shared__ __align__(16) float bsq[TM];
    __shared__ float csh[4][TM];
    __shared__ int   s_last;

    int tid  = threadIdx.x;
    int tx   = tid & 15;     // col group: cols tx*4 + c
    int ty   = tid >> 4;     // row group: rows ty*8 + r (0..7)
    int lane = tid & 31;
    int wrp  = tid >> 5;
    int bro  = bpcol(tx * 4);

    int mtot = (Mv + TM - 1) / TM;
    int mmid = (mtot + 1) >> 1;
    int mlo  = mh ? mmid : 0;
    int mhi  = mh ? mtot : mmid;

    for (int t = bxn; t < NTILE; t += GRIDN) {
        int n0 = t * TN;
        if (n0 >= Nv) break;

        // ---- load A tile (64 rows x 16 of -2a), k-transposed; asq=0.25Σv² --
        {
            int row = tid >> 1, half = tid & 1;
            int g = n0 + row;
            float4 v0 = make_float4(0.f, 0.f, 0.f, 0.f), v1 = v0;
            if (g < Nv) {
                const float4* p4 = (const float4*)(g_cA + ((size_t)b * NPTS + g) * DIM);
                v0 = p4[2 * half]; v1 = p4[2 * half + 1];
            }
            int k0 = 8 * half;
            As_t[(k0 + 0) * ASTR + row] = v0.x;
            As_t[(k0 + 1) * ASTR + row] = v0.y;
            As_t[(k0 + 2) * ASTR + row] = v0.z;
            As_t[(k0 + 3) * ASTR + row] = v0.w;
            As_t[(k0 + 4) * ASTR + row] = v1.x;
            As_t[(k0 + 5) * ASTR + row] = v1.y;
            As_t[(k0 + 6) * ASTR + row] = v1.z;
            As_t[(k0 + 7) * ASTR + row] = v1.w;
            float p = v0.x * v0.x + v0.y * v0.y + v0.z * v0.z + v0.w * v0.w
                    + v1.x * v1.x + v1.y * v1.y + v1.z * v1.z + v1.w * v1.w;
            p += __shfl_xor_sync(0xFFFFFFFFu, p, 1);
            if (half == 0) asq[row] = (g < Nv) ? (0.25f * p) : HUGEV;
        }
        __syncthreads();   // A ready (also guards As vs prev-t readers)

        ulonglong2 q0 = *(const ulonglong2*)(asq + ty * 8);
        ulonglong2 q1 = *(const ulonglong2*)(asq + ty * 8 + 4);
        ull aq2[4] = {q0.x, q0.y, q1.x, q1.y};

        float rowmin[8];
        #pragma unroll
        for (int r = 0; r < 8; r++) rowmin[r] = HUGEV;

        for (int mt = mlo; mt < mhi; mt++) {
            int m0 = mt * TM;

            // ---- load + STS B(mt): 2 threads per column ----
            {
                int col = tid >> 1, half = tid & 1;
                int pc  = bpcol(col);
                int g = m0 + col;
                float4 v0 = make_float4(0.f, 0.f, 0.f, 0.f), v1 = v0;
                if (g < Mv) {
                    const float4* p4 = (const float4*)(g_cB + ((size_t)b * NPTS + g) * DIM);
                    v0 = p4[2 * half]; v1 = p4[2 * half + 1];
                }
                int k0 = 8 * half;
                Bs_t[(k0 + 0) * BSTR + pc] = v0.x;
                Bs_t[(k0 + 1) * BSTR + pc] = v0.y;
                Bs_t[(k0 + 2) * BSTR + pc] = v0.z;
                Bs_t[(k0 + 3) * BSTR + pc] = v0.w;
                Bs_t[(k0 + 4) * BSTR + pc] = v1.x;
                Bs_t[(k0 + 5) * BSTR + pc] = v1.y;
                Bs_t[(k0 + 6) * BSTR + pc] = v1.z;
                Bs_t[(k0 + 7) * BSTR + pc] = v1.w;
                float p = v0.x * v0.x + v0.y * v0.y + v0.z * v0.z + v0.w * v0.w
                        + v1.x * v1.x + v1.y * v1.y + v1.z * v1.z + v1.w * v1.w;
                p += __shfl_xor_sync(0xFFFFFFFFu, p, 1);
                if (half == 0) bsq[col] = (g < Mv) ? p : HUGEV;
            }
            __syncthreads();   // B ready

            // ---- mainloop: acc[p][c] init=asq(rows), += (-2a)·b ----
            ull acc[4][4];
            #pragma unroll
            for (int p = 0; p < 4; p++)
                #pragma unroll
                for (int c = 0; c < 4; c++) acc[p][c] = aq2[p];

            #pragma unroll
            for (int k = 0; k < 16; k++) {
                const float* arow = As_t + k * ASTR + ty * 8;
                ulonglong2 A0 = *(const ulonglong2*)(arow);
                ulonglong2 A1 = *(const ulonglong2*)(arow + 4);
                float4 B0 = *(const float4*)(Bs_t + k * BSTR + bro);
                ull a2[4] = {A0.x, A0.y, A1.x, A1.y};
                float bs[4] = {B0.x, B0.y, B0.z, B0.w};
                #pragma unroll
                for (int c = 0; c < 4; c++) {
                    ull bb = bcast2(bs[c]);
                    #pragma unroll
                    for (int p = 0; p < 4; p++) fma2(acc[p][c], a2[p], bb);
                }
            }

            // ---- epilogue: d2 = acc + bsq, row/col mins ----
            float cm[4];
            #pragma unroll
            for (int c = 0; c < 4; c++) cm[c] = HUGEV;
            #pragma unroll
            for (int c = 0; c < 4; c++) {
                ull bb = bcast2(bsq[tx * 4 + c]);
                #pragma unroll
                for (int p = 0; p < 4; p++) {
                    ull d2 = add2(acc[p][c], bb);
                    float lo, hi;
                    unpack2(d2, lo, hi);
                    rowmin[2 * p]     = fminf(rowmin[2 * p], lo);
                    rowmin[2 * p + 1] = fminf(rowmin[2 * p + 1], hi);
                    cm[c] = fminf(cm[c], fminf(lo, hi));
                }
            }

            // ---- col-min: merge ty-pair via shfl, stage per warp ----
            #pragma unroll
            for (int c = 0; c < 4; c++) {
                float v = fmaxf(cm[c], 0.0f);   // clamp -> int-ordered atomicMin
                v = fminf(v, __shfl_xor_sync(0xFFFFFFFFu, v, 16));
                if (lane < 16) csh[wrp][tx * 4 + c] = v;
            }
            __syncthreads();   // csh ready; Bs consumers done

            if (tid < TM) {
                float v =    csh[0][tid];
                v = fminf(v, csh[1][tid]);
                v = fminf(v, csh[2][tid]);
                v = fminf(v, csh[3][tid]);
                if (m0 + tid < Mv)
                    atomicMin(&g_colmin[b * NPTS + m0 + tid], __float_as_int(v));
            }
        }

        // ---- partial row-min -> global atomicMin ----
        #pragma unroll
        for (int r = 0; r < 8; r++) {
            float v = rowmin[r];
            v = fminf(v, __shfl_xor_sync(0xFFFFFFFFu, v, 1));
            v = fminf(v, __shfl_xor_sync(0xFFFFFFFFu, v, 2));
            v = fminf(v, __shfl_xor_sync(0xFFFFFFFFu, v, 4));
            v = fminf(v, __shfl_xor_sync(0xFFFFFFFFu, v, 8));
            rowmin[r] = v;
        }
        if (tx == 0) {
            #pragma unroll
            for (int r = 0; r < 8; r++) {
                int g = n0 + ty * 8 + r;
                if (g < Nv)
                    atomicMin(&g_rowmin[b * NPTS + g],
                              __float_as_int(fmaxf(rowmin[r], 0.0f)));
            }
        }
    }

    // ---- every block arrives once; last of ARRIVALS finalizes ----
    __threadfence();
    __syncthreads();
    if (tid == 0)
        s_last = (atomicAdd(&g_done[b], 1) == ARRIVALS - 1) ? 1 : 0;
    __syncthreads();
    if (s_last) {
        float s = 0.0f;
        for (int n = tid; n < Nv; n += NTHR) {
            float v = __int_as_float(__ldcg(&g_rowmin[b * NPTS + n]));
            v = (v >= 1e29f) ? BIG2 : v;
            s += v * g_wA[b * NPTS + n];
        }
        for (int m = tid; m < Mv; m += NTHR) {
            float v = __int_as_float(__ldcg(&g_colmin[b * NPTS + m]));
            v = (v >= 1e29f) ? BIG2 : v;
            s += v * g_wB[b * NPTS + m];
        }
        #pragma unroll
        for (int d = 16; d > 0; d >>= 1)
            s += __shfl_xor_sync(0xFFFFFFFFu, s, d);
        __shared__ float wred[4];
        if (lane == 0) wred[wrp] = s;
        __syncthreads();
        if (tid == 0)
            out[b] = wred[0] + wred[1] + wred[2] + wred[3];
    }
}

// ---------------- launch ----------------
extern "C" void kernel_launch(void* const* d_in, const int* in_sizes, int n_in,
                              void* d_out, int out_size) {
    const float* ow = (const float*)d_in[0];  // [B, N]
    const float* op = (const float*)d_in[1];  // [B, N, D]
    const float* tw = (const float*)d_in[2];  // [B, M]
    const float* tp = (const float*)d_in[3];  // [B, M, D]
    float* out = (float*)d_out;               // [B]

    setup_kernel<<<2 * BATCH, 256>>>(ow, op, tw, tp, out);
    dim3 grid(GRIDN * MSPLIT, BATCH);
    pair_kernel<<<grid, NTHR>>>(out);
}

// round 15
// speedup vs baseline: 1.2812x; 1.0775x over previous
#include <cuda_runtime.h>
#include <cuda_bf16.h>
#include <cstdint>

#define BATCH 32
#define NPTS  2048
#define DIM   16
#define BIG2  1.0e16f
#define HUGEV 1.0e30f
#define RSTR  144            // smem bytes per 64-col bf16 row (128 + 16 pad)

typedef unsigned long long ull;
typedef unsigned int u32;

// ---------------- scratch (no allocs allowed) ----------------
__device__ u32   g_bfA[BATCH * NPTS * 32];   // augmented bf16 rows, role 0
__device__ u32   g_bfB[BATCH * NPTS * 32];   // augmented bf16 rows, role 1
__device__ float g_wA[BATCH * NPTS];
__device__ float g_wB[BATCH * NPTS];
__device__ int   g_cntA[BATCH];
__device__ int   g_cntB[BATCH];
__device__ float g_minA[BATCH * NPTS];       // per-output min d^2 (exact per CTA)
__device__ int   g_colmin[BATCH * NPTS];     // float-as-int (nonneg), +inf init

__device__ __forceinline__ u32 pkbf(__nv_bfloat16 a, __nv_bfloat16 b) {
    return (u32)__bfloat16_as_ushort(a) | ((u32)__bfloat16_as_ushort(b) << 16);
}

__device__ __forceinline__ void mma16816(float* d, const u32* a, u32 b0, u32 b1) {
    asm volatile(
        "mma.sync.aligned.m16n8k16.row.col.f32.bf16.bf16.f32 "
        "{%0,%1,%2,%3}, {%4,%5,%6,%7}, {%8,%9}, {%0,%1,%2,%3};"
        : "+f"(d[0]), "+f"(d[1]), "+f"(d[2]), "+f"(d[3])
        : "r"(a[0]), "r"(a[1]), "r"(a[2]), "r"(a[3]), "r"(b0), "r"(b1));
}

// ---------------- setup: compaction + bf16 hi/lo conversion ----------------
// Augmented 64-col bf16 rows. Segment layout is ROLE-DEPENDENT:
//   role 0 (A/outputs): [-2a_hi | -2a_lo | -2a_hi | sq_hi,sq_lo,1,1 | 0...]
//   role 1 (B/targets): [  b_hi |   b_hi |   b_lo | 1,1,sq_hi,sq_lo | 0...]
// Dot over 64 cols = -2*(ah*bh + al*bh + ah*bl) + asq + bsq  (= d^2 up to al*bl)
__global__ __launch_bounds__(256) void setup_kernel(
    const float* __restrict__ ow, const float* __restrict__ op,
    const float* __restrict__ tw, const float* __restrict__ tp) {
    int blk = blockIdx.x;              // 64 blocks: (b, sel)
    int b   = blk >> 1;
    int sel = blk & 1;
    int tid = threadIdx.x, lane = tid & 31, wrp = tid >> 5;

    if (sel == 1) {  // init colmin slice
        for (int i = tid; i < NPTS; i += 256)
            g_colmin[b * NPTS + i] = 0x7F800000;
    }

    const float* w   = sel ? tw : ow;
    const float* pts = sel ? tp : op;
    u32*   dstP = sel ? g_bfB : g_bfA;
    float* dstW = sel ? g_wB : g_wA;
    int*   cnt  = sel ? g_cntB : g_cntA;

    int i0 = tid * 8;
    float wv[8];
    int c = 0;
    #pragma unroll
    for (int k = 0; k < 8; k++) {
        wv[k] = w[b * NPTS + i0 + k];
        c += (wv[k] != 0.0f);
    }
    int incl = c;
    #pragma unroll
    for (int d = 1; d < 32; d <<= 1) {
        int n = __shfl_up_sync(0xFFFFFFFFu, incl, d);
        if (lane >= d) incl += n;
    }
    __shared__ int wtot[8], wbase[8], s_cnt;
    if (lane == 31) wtot[wrp] = incl;
    __syncthreads();
    if (tid == 0) {
        int s = 0;
        #pragma unroll
        for (int wI = 0; wI < 8; wI++) { wbase[wI] = s; s += wtot[wI]; }
        cnt[b] = s; s_cnt = s;
    }
    __syncthreads();
    int p = wbase[wrp] + incl - c;
    #pragma unroll
    for (int k = 0; k < 8; k++) {
        if (wv[k] != 0.0f) {
            const float4* s4 = (const float4*)(pts + ((size_t)b * NPTS + i0 + k) * DIM);
            float xv[16];
            #pragma unroll
            for (int q = 0; q < 4; q++) {
                float4 v = s4[q];
                xv[4*q+0] = v.x; xv[4*q+1] = v.y; xv[4*q+2] = v.z; xv[4*q+3] = v.w;
            }
            float sq = 0.0f;
            #pragma unroll
            for (int e = 0; e < 16; e++) sq += xv[e] * xv[e];

            __nv_bfloat16 h[16], l[16];
            #pragma unroll
            for (int e = 0; e < 16; e++) {
                __nv_bfloat16 hh = __float2bfloat16(xv[e]);
                float hf = __bfloat162float(hh);
                __nv_bfloat16 ll = __float2bfloat16(xv[e] - hf);
                if (sel == 0) {   // role 0: scale hi/lo by -2 (exact)
                    hh = __float2bfloat16(-2.0f * hf);
                    ll = __float2bfloat16(-2.0f * __bfloat162float(ll));
                }
                h[e] = hh; l[e] = ll;
            }
            __nv_bfloat16 sqh = __float2bfloat16(sq);
            __nv_bfloat16 sql = __float2bfloat16(sq - __bfloat162float(sqh));
            __nv_bfloat16 one = __float2bfloat16(1.0f);

            u32 H[8], L[8];
            #pragma unroll
            for (int j = 0; j < 8; j++) {
                H[j] = pkbf(h[2*j], h[2*j+1]);
                L[j] = pkbf(l[2*j], l[2*j+1]);
            }
            uint4* d16 = (uint4*)(dstP + ((size_t)b * NPTS + p) * 32);
            // segment 0 (cols 0-15): hi for both roles
            d16[0] = make_uint4(H[0], H[1], H[2], H[3]);
            d16[1] = make_uint4(H[4], H[5], H[6], H[7]);
            if (sel == 0) {
                // A: segment 1 = lo, segment 2 = hi
                d16[2] = make_uint4(L[0], L[1], L[2], L[3]);
                d16[3] = make_uint4(L[4], L[5], L[6], L[7]);
                d16[4] = make_uint4(H[0], H[1], H[2], H[3]);
                d16[5] = make_uint4(H[4], H[5], H[6], H[7]);
            } else {
                // B: segment 1 = hi, segment 2 = lo
                d16[2] = make_uint4(H[0], H[1], H[2], H[3]);
                d16[3] = make_uint4(H[4], H[5], H[6], H[7]);
                d16[4] = make_uint4(L[0], L[1], L[2], L[3]);
                d16[5] = make_uint4(L[4], L[5], L[6], L[7]);
            }
            u32 w24 = (sel == 0) ? pkbf(sqh, sql) : pkbf(one, one);
            u32 w25 = (sel == 0) ? pkbf(one, one) : pkbf(sqh, sql);
            d16[6] = make_uint4(w24, w25, 0u, 0u);
            d16[7] = make_uint4(0u, 0u, 0u, 0u);
            dstW[b * NPTS + p] = wv[k];
            p++;
        }
    }
    __syncthreads();
    // sentinel rows [cnt, 2048): zeros except own-sq slot = 1e30
    {
        __nv_bfloat16 big = __float2bfloat16(HUGEV);
        __nv_bfloat16 one = __float2bfloat16(1.0f);
        __nv_bfloat16 zer = __float2bfloat16(0.0f);
        u32 w24 = (sel == 0) ? pkbf(big, zer) : pkbf(one, one);
        u32 w25 = (sel == 0) ? pkbf(one, one) : pkbf(big, zer);
        for (int i = s_cnt + tid; i < NPTS; i += 256) {
            uint4* d16 = (uint4*)(dstP + ((size_t)b * NPTS + i) * 32);
            uint4 z = make_uint4(0u, 0u, 0u, 0u);
            d16[0] = z; d16[1] = z; d16[2] = z; d16[3] = z; d16[4] = z; d16[5] = z;
            d16[6] = make_uint4(w24, w25, 0u, 0u);
            d16[7] = z;
        }
    }
}

// --------- pair kernel: mma.sync bf16, D = d^2 in registers ----------------
// CTA: 128 A-rows x full M. 8 warps: wrow = wid&3 (32 rows), cg = wid>>2 (64 cols).
__global__ __launch_bounds__(256, 2) void mma_pair_kernel() {
    int b  = blockIdx.y;
    int Nv = g_cntA[b];
    int Mv = g_cntB[b];
    int n0 = blockIdx.x * 128;
    if (n0 >= Nv) return;

    __shared__ __align__(16) char Asm[128 * RSTR];
    __shared__ __align__(16) char Bsm[128 * RSTR];
    __shared__ float csh[4][128];
    __shared__ float rsh[2][128];

    int tid  = threadIdx.x;
    int lane = tid & 31;
    int wid  = tid >> 5;
    int wrow = wid & 3;        // row group (32 rows)
    int cg   = wid >> 2;       // col half (64 cols)
    int gid  = lane >> 2;      // 0..7
    int tig  = lane & 3;       // 0..3

    // ---- load A tile (128 rows x 128B), 2 threads per row ----
    {
        int row = tid >> 1, half = tid & 1;
        const uint4* s = (const uint4*)(g_bfA + ((size_t)b * NPTS + n0 + row) * 32) + half * 4;
        uint4* d = (uint4*)(Asm + row * RSTR + half * 64);
        d[0] = s[0]; d[1] = s[1]; d[2] = s[2]; d[3] = s[3];
    }

    float rmin[4] = {HUGEV, HUGEV, HUGEV, HUGEV};
    int mtiles = (Mv + 127) >> 7;

    const char* Aw = Asm + (wrow * 32 + gid) * RSTR + tig * 4;

    for (int mt = 0; mt < mtiles; mt++) {
        int m0 = mt * 128;
        // ---- load B tile ----
        {
            int row = tid >> 1, half = tid & 1;
            const uint4* s = (const uint4*)(g_bfB + ((size_t)b * NPTS + m0 + row) * 32) + half * 4;
            uint4* d = (uint4*)(Bsm + row * RSTR + half * 64);
            d[0] = s[0]; d[1] = s[1]; d[2] = s[2]; d[3] = s[3];
        }
        __syncthreads();

        float acc[2][8][4];
        #pragma unroll
        for (int mi = 0; mi < 2; mi++)
            #pragma unroll
            for (int nj = 0; nj < 8; nj++)
                #pragma unroll
                for (int q = 0; q < 4; q++) acc[mi][nj][q] = 0.0f;

        const char* Bw = Bsm + (cg * 64 + gid) * RSTR + tig * 4;
        #pragma unroll
        for (int ks = 0; ks < 4; ks++) {
            u32 a[2][4];
            #pragma unroll
            for (int mi = 0; mi < 2; mi++) {
                const char* ab = Aw + mi * 16 * RSTR + ks * 32;
                a[mi][0] = *(const u32*)(ab);
                a[mi][1] = *(const u32*)(ab + 8 * RSTR);
                a[mi][2] = *(const u32*)(ab + 16);
                a[mi][3] = *(const u32*)(ab + 8 * RSTR + 16);
            }
            #pragma unroll
            for (int nj = 0; nj < 8; nj++) {
                const char* bb = Bw + nj * 8 * RSTR + ks * 32;
                u32 b0 = *(const u32*)(bb);
                u32 b1 = *(const u32*)(bb + 16);
                mma16816(acc[0][nj], a[0], b0, b1);
                mma16816(acc[1][nj], a[1], b0, b1);
            }
        }

        // ---- epilogue: row/col mins from register accumulators ----
        #pragma unroll
        for (int nj = 0; nj < 8; nj++) {
            float cm0 = fminf(fminf(acc[0][nj][0], acc[0][nj][2]),
                              fminf(acc[1][nj][0], acc[1][nj][2]));
            float cm1 = fminf(fminf(acc[0][nj][1], acc[0][nj][3]),
                              fminf(acc[1][nj][1], acc[1][nj][3]));
            #pragma unroll
            for (int mi = 0; mi < 2; mi++) {
                rmin[2*mi]   = fminf(rmin[2*mi],
                                     fminf(acc[mi][nj][0], acc[mi][nj][1]));
                rmin[2*mi+1] = fminf(rmin[2*mi+1],
                                     fminf(acc[mi][nj][2], acc[mi][nj][3]));
            }
            cm0 = fmaxf(cm0, 0.0f);
            cm1 = fmaxf(cm1, 0.0f);
            #pragma unroll
            for (int d = 4; d < 32; d <<= 1) {
                cm0 = fminf(cm0, __shfl_xor_sync(0xFFFFFFFFu, cm0, d));
                cm1 = fminf(cm1, __shfl_xor_sync(0xFFFFFFFFu, cm1, d));
            }
            if (gid == 0) {
                csh[wrow][cg * 64 + nj * 8 + tig * 2]     = cm0;
                csh[wrow][cg * 64 + nj * 8 + tig * 2 + 1] = cm1;
            }
        }
        __syncthreads();   // csh ready; Bsm consumers done (mma is sync)
        if (tid < 128) {
            float v = fminf(fminf(csh[0][tid], csh[1][tid]),
                            fminf(csh[2][tid], csh[3][tid]));
            if (m0 + tid < Mv)
                atomicMin(&g_colmin[b * NPTS + m0 + tid], __float_as_int(v));
        }
        __syncthreads();   // csh free for next iter epilogue
    }

    // ---- row mins: reduce across tig lanes, merge col halves ----
    #pragma unroll
    for (int r = 0; r < 4; r++) {
        rmin[r] = fminf(rmin[r], __shfl_xor_sync(0xFFFFFFFFu, rmin[r], 1));
        rmin[r] = fminf(rmin[r], __shfl_xor_sync(0xFFFFFFFFu, rmin[r], 2));
    }
    if (tig == 0) {
        #pragma unroll
        for (int mi = 0; mi < 2; mi++) {
            rsh[cg][wrow * 32 + mi * 16 + gid]     = rmin[2*mi];
            rsh[cg][wrow * 32 + mi * 16 + gid + 8] = rmin[2*mi+1];
        }
    }
    __syncthreads();
    if (tid < 128)
        g_minA[b * NPTS + n0 + tid] =
            fmaxf(fminf(rsh[0][tid], rsh[1][tid]), 0.0f);
}

// ---------------- finalize: weighted sums of per-point mins ----------------
__global__ __launch_bounds__(256) void finalize_kernel(float* out) {
    int b = blockIdx.x, tid = threadIdx.x, lane = tid & 31, wrp = tid >> 5;
    int NvA = g_cntA[b], NvB = g_cntB[b];
    float s = 0.0f;
    for (int n = tid; n < NvA; n += 256) {
        float v = g_minA[b * NPTS + n];
        v = (v >= 1e29f) ? BIG2 : v;
        s += v * g_wA[b * NPTS + n];
    }
    for (int m = tid; m < NvB; m += 256) {
        float v = __int_as_float(g_colmin[b * NPTS + m]);
        v = (v >= 1e29f) ? BIG2 : v;
        s += v * g_wB[b * NPTS + m];
    }
    #pragma unroll
    for (int d = 16; d > 0; d >>= 1)
        s += __shfl_xor_sync(0xFFFFFFFFu, s, d);
    __shared__ float wred[8];
    if (lane == 0) wred[wrp] = s;
    __syncthreads();
    if (tid == 0) {
        float t = 0.0f;
        #pragma unroll
        for (int wI = 0; wI < 8; wI++) t += wred[wI];
        out[b] = t;
    }
}

// ---------------- launch ----------------
extern "C" void kernel_launch(void* const* d_in, const int* in_sizes, int n_in,
                              void* d_out, int out_size) {
    const float* ow = (const float*)d_in[0];  // [B, N]
    const float* op = (const float*)d_in[1];  // [B, N, D]
    const float* tw = (const float*)d_in[2];  // [B, M]
    const float* tp = (const float*)d_in[3];  // [B, M, D]
    float* out = (float*)d_out;               // [B]

    setup_kernel<<<2 * BATCH, 256>>>(ow, op, tw, tp);
    dim3 grid(NPTS / 128, BATCH);             // 16 row slots x 32 batches
    mma_pair_kernel<<<grid, 256>>>();
    finalize_kernel<<<BATCH, 256>>>(out);
}

// round 16
// speedup vs baseline: 1.4484x; 1.1304x over previous
#include <cuda_runtime.h>
#include <cuda_bf16.h>
#include <cstdint>

#define BATCH 32
#define NPTS  2048
#define DIM   16
#define BIG2  1.0e16f
#define HUGEV 1.0e30f
#define RSTR  144            // smem bytes per 64-col bf16 row (128 + 16 pad)

typedef unsigned long long ull;
typedef unsigned int u32;

// ---------------- scratch (no allocs allowed) ----------------
__device__ u32   g_bfA[BATCH * NPTS * 32];   // augmented bf16 rows, role 0
__device__ u32   g_bfB[BATCH * NPTS * 32];   // augmented bf16 rows, role 1
__device__ float g_wA[BATCH * NPTS];
__device__ float g_wB[BATCH * NPTS];
__device__ int   g_cntA[BATCH];
__device__ int   g_cntB[BATCH];
__device__ float g_minA[BATCH * NPTS];       // per-output min d^2 (exact per CTA)
__device__ int   g_colmin[BATCH * NPTS];     // float-as-int (nonneg), +inf init

__device__ __forceinline__ u32 pkbf(__nv_bfloat16 a, __nv_bfloat16 b) {
    return (u32)__bfloat16_as_ushort(a) | ((u32)__bfloat16_as_ushort(b) << 16);
}

__device__ __forceinline__ void mma16816(float* d, const u32* a, u32 b0, u32 b1) {
    asm volatile(
        "mma.sync.aligned.m16n8k16.row.col.f32.bf16.bf16.f32 "
        "{%0,%1,%2,%3}, {%4,%5,%6,%7}, {%8,%9}, {%0,%1,%2,%3};"
        : "+f"(d[0]), "+f"(d[1]), "+f"(d[2]), "+f"(d[3])
        : "r"(a[0]), "r"(a[1]), "r"(a[2]), "r"(a[3]), "r"(b0), "r"(b1));
}

// Convert one fp32 point to the augmented 64-col bf16 row.
//   role 0 (A/outputs): [-2a_hi | -2a_lo | -2a_hi | sq_hi,sq_lo,1,1 | 0...]
//   role 1 (B/targets): [  b_hi |   b_hi |   b_lo | 1,1,sq_hi,sq_lo | 0...]
// Dot over 64 cols = -2*(ah*bh + al*bh + ah*bl) + asq + bsq (= d^2 up to al*bl)
__device__ __forceinline__ void convert_row(uint4* d16, const float4* s4, int sel) {
    float xv[16];
    #pragma unroll
    for (int q = 0; q < 4; q++) {
        float4 v = s4[q];
        xv[4*q+0] = v.x; xv[4*q+1] = v.y; xv[4*q+2] = v.z; xv[4*q+3] = v.w;
    }
    float sq = 0.0f;
    #pragma unroll
    for (int e = 0; e < 16; e++) sq += xv[e] * xv[e];

    __nv_bfloat16 h[16], l[16];
    #pragma unroll
    for (int e = 0; e < 16; e++) {
        __nv_bfloat16 hh = __float2bfloat16(xv[e]);
        float hf = __bfloat162float(hh);
        __nv_bfloat16 ll = __float2bfloat16(xv[e] - hf);
        if (sel == 0) {   // role 0: scale hi/lo by -2 (exact)
            hh = __float2bfloat16(-2.0f * hf);
            ll = __float2bfloat16(-2.0f * __bfloat162float(ll));
        }
        h[e] = hh; l[e] = ll;
    }
    __nv_bfloat16 sqh = __float2bfloat16(sq);
    __nv_bfloat16 sql = __float2bfloat16(sq - __bfloat162float(sqh));
    __nv_bfloat16 one = __float2bfloat16(1.0f);

    u32 H[8], L[8];
    #pragma unroll
    for (int j = 0; j < 8; j++) {
        H[j] = pkbf(h[2*j], h[2*j+1]);
        L[j] = pkbf(l[2*j], l[2*j+1]);
    }
    d16[0] = make_uint4(H[0], H[1], H[2], H[3]);
    d16[1] = make_uint4(H[4], H[5], H[6], H[7]);
    if (sel == 0) {
        d16[2] = make_uint4(L[0], L[1], L[2], L[3]);
        d16[3] = make_uint4(L[4], L[5], L[6], L[7]);
        d16[4] = make_uint4(H[0], H[1], H[2], H[3]);
        d16[5] = make_uint4(H[4], H[5], H[6], H[7]);
    } else {
        d16[2] = make_uint4(H[0], H[1], H[2], H[3]);
        d16[3] = make_uint4(H[4], H[5], H[6], H[7]);
        d16[4] = make_uint4(L[0], L[1], L[2], L[3]);
        d16[5] = make_uint4(L[4], L[5], L[6], L[7]);
    }
    u32 w24 = (sel == 0) ? pkbf(sqh, sql) : pkbf(one, one);
    u32 w25 = (sel == 0) ? pkbf(one, one) : pkbf(sqh, sql);
    d16[6] = make_uint4(w24, w25, 0u, 0u);
    d16[7] = make_uint4(0u, 0u, 0u, 0u);
}

// ---------------- setup: compaction + conversion, 1024 thr/block ----------
__global__ __launch_bounds__(1024) void setup_kernel(
    const float* __restrict__ ow, const float* __restrict__ op,
    const float* __restrict__ tw, const float* __restrict__ tp) {
    int blk = blockIdx.x;              // 64 blocks: (b, sel)
    int b   = blk >> 1;
    int sel = blk & 1;
    int tid = threadIdx.x, lane = tid & 31, wrp = tid >> 5;

    const float* w   = sel ? tw : ow;
    const float* pts = sel ? tp : op;
    u32*   dstP = sel ? g_bfB : g_bfA;
    float* dstW = sel ? g_wB : g_wA;
    int*   cnt  = sel ? g_cntB : g_cntA;

    // each thread owns 2 contiguous points
    int i0 = tid * 2;
    float wv0 = w[b * NPTS + i0];
    float wv1 = w[b * NPTS + i0 + 1];
    int c = (wv0 != 0.0f) + (wv1 != 0.0f);

    int incl = c;
    #pragma unroll
    for (int d = 1; d < 32; d <<= 1) {
        int n = __shfl_up_sync(0xFFFFFFFFu, incl, d);
        if (lane >= d) incl += n;
    }
    __shared__ int wtot[32], wbase[32], s_cnt;
    if (lane == 31) wtot[wrp] = incl;
    __syncthreads();
    if (tid == 0) {
        int s = 0;
        #pragma unroll
        for (int wI = 0; wI < 32; wI++) { wbase[wI] = s; s += wtot[wI]; }
        cnt[b] = s; s_cnt = s;
    }
    __syncthreads();
    int p = wbase[wrp] + incl - c;

    if (wv0 != 0.0f) {
        convert_row((uint4*)(dstP + ((size_t)b * NPTS + p) * 32),
                    (const float4*)(pts + ((size_t)b * NPTS + i0) * DIM), sel);
        dstW[b * NPTS + p] = wv0;
        p++;
    }
    if (wv1 != 0.0f) {
        convert_row((uint4*)(dstP + ((size_t)b * NPTS + p) * 32),
                    (const float4*)(pts + ((size_t)b * NPTS + i0 + 1) * DIM), sel);
        dstW[b * NPTS + p] = wv1;
    }

    // sentinel rows: only [cnt, ceil128(cnt)) are ever read by the pair kernel
    int lim = (s_cnt + 127) & ~127;
    if (lim > NPTS) lim = NPTS;
    {
        __nv_bfloat16 big = __float2bfloat16(HUGEV);
        __nv_bfloat16 one = __float2bfloat16(1.0f);
        __nv_bfloat16 zer = __float2bfloat16(0.0f);
        u32 w24 = (sel == 0) ? pkbf(big, zer) : pkbf(one, one);
        u32 w25 = (sel == 0) ? pkbf(one, one) : pkbf(big, zer);
        for (int i = s_cnt + tid; i < lim; i += 1024) {
            uint4* d16 = (uint4*)(dstP + ((size_t)b * NPTS + i) * 32);
            uint4 z = make_uint4(0u, 0u, 0u, 0u);
            d16[0] = z; d16[1] = z; d16[2] = z; d16[3] = z; d16[4] = z; d16[5] = z;
            d16[6] = make_uint4(w24, w25, 0u, 0u);
            d16[7] = z;
        }
    }
    // colmin init: reads/writes are guarded by < Mv, so [0, cnt) suffices
    if (sel == 1) {
        for (int i = tid; i < s_cnt; i += 1024)
            g_colmin[b * NPTS + i] = 0x7F800000;
    }
}

// --------- pair kernel: mma.sync bf16, D = d^2 in registers ----------------
// CTA: 128 A-rows x full M. 8 warps: wrow = wid&3 (32 rows), cg = wid>>2 (64 cols).
__global__ __launch_bounds__(256, 2) void mma_pair_kernel() {
    int b  = blockIdx.y;
    int Nv = g_cntA[b];
    int Mv = g_cntB[b];
    int n0 = blockIdx.x * 128;
    if (n0 >= Nv) return;

    __shared__ __align__(16) char Asm[128 * RSTR];
    __shared__ __align__(16) char Bsm[128 * RSTR];
    __shared__ float csh[4][128];
    __shared__ float rsh[2][128];

    int tid  = threadIdx.x;
    int lane = tid & 31;
    int wid  = tid >> 5;
    int wrow = wid & 3;        // row group (32 rows)
    int cg   = wid >> 2;       // col half (64 cols)
    int gid  = lane >> 2;      // 0..7
    int tig  = lane & 3;       // 0..3

    // ---- load A tile (128 rows x 128B), 2 threads per row ----
    {
        int row = tid >> 1, half = tid & 1;
        const uint4* s = (const uint4*)(g_bfA + ((size_t)b * NPTS + n0 + row) * 32) + half * 4;
        uint4* d = (uint4*)(Asm + row * RSTR + half * 64);
        d[0] = s[0]; d[1] = s[1]; d[2] = s[2]; d[3] = s[3];
    }

    float rmin[4] = {HUGEV, HUGEV, HUGEV, HUGEV};
    int mtiles = (Mv + 127) >> 7;

    const char* Aw = Asm + (wrow * 32 + gid) * RSTR + tig * 4;

    for (int mt = 0; mt < mtiles; mt++) {
        int m0 = mt * 128;
        // ---- load B tile ----
        {
            int row = tid >> 1, half = tid & 1;
            const uint4* s = (const uint4*)(g_bfB + ((size_t)b * NPTS + m0 + row) * 32) + half * 4;
            uint4* d = (uint4*)(Bsm + row * RSTR + half * 64);
            d[0] = s[0]; d[1] = s[1]; d[2] = s[2]; d[3] = s[3];
        }
        __syncthreads();

        float acc[2][8][4];
        #pragma unroll
        for (int mi = 0; mi < 2; mi++)
            #pragma unroll
            for (int nj = 0; nj < 8; nj++)
                #pragma unroll
                for (int q = 0; q < 4; q++) acc[mi][nj][q] = 0.0f;

        const char* Bw = Bsm + (cg * 64 + gid) * RSTR + tig * 4;
        #pragma unroll
        for (int ks = 0; ks < 4; ks++) {
            u32 a[2][4];
            #pragma unroll
            for (int mi = 0; mi < 2; mi++) {
                const char* ab = Aw + mi * 16 * RSTR + ks * 32;
                a[mi][0] = *(const u32*)(ab);
                a[mi][1] = *(const u32*)(ab + 8 * RSTR);
                a[mi][2] = *(const u32*)(ab + 16);
                a[mi][3] = *(const u32*)(ab + 8 * RSTR + 16);
            }
            #pragma unroll
            for (int nj = 0; nj < 8; nj++) {
                const char* bb = Bw + nj * 8 * RSTR + ks * 32;
                u32 b0 = *(const u32*)(bb);
                u32 b1 = *(const u32*)(bb + 16);
                mma16816(acc[0][nj], a[0], b0, b1);
                mma16816(acc[1][nj], a[1], b0, b1);
            }
        }

        // ---- epilogue: row/col mins from register accumulators ----
        #pragma unroll
        for (int nj = 0; nj < 8; nj++) {
            float cm0 = fminf(fminf(acc[0][nj][0], acc[0][nj][2]),
                              fminf(acc[1][nj][0], acc[1][nj][2]));
            float cm1 = fminf(fminf(acc[0][nj][1], acc[0][nj][3]),
                              fminf(acc[1][nj][1], acc[1][nj][3]));
            #pragma unroll
            for (int mi = 0; mi < 2; mi++) {
                rmin[2*mi]   = fminf(rmin[2*mi],
                                     fminf(acc[mi][nj][0], acc[mi][nj][1]));
                rmin[2*mi+1] = fminf(rmin[2*mi+1],
                                     fminf(acc[mi][nj][2], acc[mi][nj][3]));
            }
            cm0 = fmaxf(cm0, 0.0f);
            cm1 = fmaxf(cm1, 0.0f);
            #pragma unroll
            for (int d = 4; d < 32; d <<= 1) {
                cm0 = fminf(cm0, __shfl_xor_sync(0xFFFFFFFFu, cm0, d));
                cm1 = fminf(cm1, __shfl_xor_sync(0xFFFFFFFFu, cm1, d));
            }
            if (gid == 0) {
                csh[wrow][cg * 64 + nj * 8 + tig * 2]     = cm0;
                csh[wrow][cg * 64 + nj * 8 + tig * 2 + 1] = cm1;
            }
        }
        __syncthreads();   // csh ready; Bsm consumers done (mma is sync)
        if (tid < 128) {
            float v = fminf(fminf(csh[0][tid], csh[1][tid]),
                            fminf(csh[2][tid], csh[3][tid]));
            if (m0 + tid < Mv)
                atomicMin(&g_colmin[b * NPTS + m0 + tid], __float_as_int(v));
        }
        __syncthreads();   // csh free for next iter epilogue
    }

    // ---- row mins: reduce across tig lanes, merge col halves ----
    #pragma unroll
    for (int r = 0; r < 4; r++) {
        rmin[r] = fminf(rmin[r], __shfl_xor_sync(0xFFFFFFFFu, rmin[r], 1));
        rmin[r] = fminf(rmin[r], __shfl_xor_sync(0xFFFFFFFFu, rmin[r], 2));
    }
    if (tig == 0) {
        #pragma unroll
        for (int mi = 0; mi < 2; mi++) {
            rsh[cg][wrow * 32 + mi * 16 + gid]     = rmin[2*mi];
            rsh[cg][wrow * 32 + mi * 16 + gid + 8] = rmin[2*mi+1];
        }
    }
    __syncthreads();
    if (tid < 128)
        g_minA[b * NPTS + n0 + tid] =
            fmaxf(fminf(rsh[0][tid], rsh[1][tid]), 0.0f);
}

// ---------------- finalize: weighted sums of per-point mins ----------------
__global__ __launch_bounds__(256) void finalize_kernel(float* out) {
    int b = blockIdx.x, tid = threadIdx.x, lane = tid & 31, wrp = tid >> 5;
    int NvA = g_cntA[b], NvB = g_cntB[b];
    float s = 0.0f;
    for (int n = tid; n < NvA; n += 256) {
        float v = g_minA[b * NPTS + n];
        v = (v >= 1e29f) ? BIG2 : v;
        s += v * g_wA[b * NPTS + n];
    }
    for (int m = tid; m < NvB; m += 256) {
        float v = __int_as_float(g_colmin[b * NPTS + m]);
        v = (v >= 1e29f) ? BIG2 : v;
        s += v * g_wB[b * NPTS + m];
    }
    #pragma unroll
    for (int d = 16; d > 0; d >>= 1)
        s += __shfl_xor_sync(0xFFFFFFFFu, s, d);
    __shared__ float wred[8];
    if (lane == 0) wred[wrp] = s;
    __syncthreads();
    if (tid == 0) {
        float t = 0.0f;
        #pragma unroll
        for (int wI = 0; wI < 8; wI++) t += wred[wI];
        out[b] = t;
    }
}

// ---------------- launch ----------------
extern "C" void kernel_launch(void* const* d_in, const int* in_sizes, int n_in,
                              void* d_out, int out_size) {
    const float* ow = (const float*)d_in[0];  // [B, N]
    const float* op = (const float*)d_in[1];  // [B, N, D]
    const float* tw = (const float*)d_in[2];  // [B, M]
    const float* tp = (const float*)d_in[3];  // [B, M, D]
    float* out = (float*)d_out;               // [B]

    setup_kernel<<<2 * BATCH, 1024>>>(ow, op, tw, tp);
    dim3 grid(NPTS / 128, BATCH);             // 16 row slots x 32 batches
    mma_pair_kernel<<<grid, 256>>>();
    finalize_kernel<<<BATCH, 256>>>(out);
}

// round 17
// speedup vs baseline: 1.5131x; 1.0447x over previous
#include <cuda_runtime.h>
#include <cuda_bf16.h>
#include <cstdint>

#define BATCH 32
#define NPTS  2048
#define DIM   16
#define BIG2  1.0e16f
#define HUGEV 1.0e30f
#define RSTR  144            // smem bytes per 64-col bf16 row (128 + 16 pad)

typedef unsigned long long ull;
typedef unsigned int u32;

// ---------------- scratch (no allocs allowed) ----------------
__device__ u32   g_bfA[BATCH * NPTS * 32];   // augmented bf16 rows, role 0
__device__ u32   g_bfB[BATCH * NPTS * 32];   // augmented bf16 rows, role 1
__device__ int   g_srcA[BATCH * NPTS];       // compacted row -> source row
__device__ int   g_srcB[BATCH * NPTS];
__device__ float g_wA[BATCH * NPTS];
__device__ float g_wB[BATCH * NPTS];
__device__ int   g_cntA[BATCH];
__device__ int   g_cntB[BATCH];
__device__ float g_minA[BATCH * NPTS];       // per-output min d^2
__device__ int   g_colmin[BATCH * NPTS];     // float-as-int (nonneg), +inf init
__device__ int   g_done[BATCH];

__device__ __forceinline__ u32 pkbf(__nv_bfloat16 a, __nv_bfloat16 b) {
    return (u32)__bfloat16_as_ushort(a) | ((u32)__bfloat16_as_ushort(b) << 16);
}

__device__ __forceinline__ void mma16816(float* d, const u32* a, u32 b0, u32 b1) {
    asm volatile(
        "mma.sync.aligned.m16n8k16.row.col.f32.bf16.bf16.f32 "
        "{%0,%1,%2,%3}, {%4,%5,%6,%7}, {%8,%9}, {%0,%1,%2,%3};"
        : "+f"(d[0]), "+f"(d[1]), "+f"(d[2]), "+f"(d[3])
        : "r"(a[0]), "r"(a[1]), "r"(a[2]), "r"(a[3]), "r"(b0), "r"(b1));
}

// ---------------- scan: compaction index map (1 block per (b,sel)) --------
__global__ __launch_bounds__(1024) void scan_kernel(
    const float* __restrict__ ow, const float* __restrict__ tw) {
    int blk = blockIdx.x;              // 64 blocks: (b, sel)
    int b   = blk >> 1;
    int sel = blk & 1;
    int tid = threadIdx.x, lane = tid & 31, wrp = tid >> 5;

    const float* w = sel ? tw : ow;
    int*   src  = sel ? g_srcB : g_srcA;
    float* dstW = sel ? g_wB : g_wA;
    int*   cnt  = sel ? g_cntB : g_cntA;

    int i0 = tid * 2;
    float wv0 = w[b * NPTS + i0];
    float wv1 = w[b * NPTS + i0 + 1];
    int c = (wv0 != 0.0f) + (wv1 != 0.0f);

    int incl = c;
    #pragma unroll
    for (int d = 1; d < 32; d <<= 1) {
        int n = __shfl_up_sync(0xFFFFFFFFu, incl, d);
        if (lane >= d) incl += n;
    }
    __shared__ int wtot[32], wbase[32], s_cnt;
    if (lane == 31) wtot[wrp] = incl;
    __syncthreads();
    if (tid == 0) {
        int s = 0;
        #pragma unroll
        for (int wI = 0; wI < 32; wI++) { wbase[wI] = s; s += wtot[wI]; }
        cnt[b] = s; s_cnt = s;
        if (sel == 0) g_done[b] = 0;
    }
    __syncthreads();
    int p = wbase[wrp] + incl - c;
    if (wv0 != 0.0f) { src[b * NPTS + p] = i0;     dstW[b * NPTS + p] = wv0; p++; }
    if (wv1 != 0.0f) { src[b * NPTS + p] = i0 + 1; dstW[b * NPTS + p] = wv1; }

    if (sel == 1) {
        for (int i = tid; i < s_cnt; i += 1024)
            g_colmin[b * NPTS + i] = 0x7F800000;
    }
}

// ---------------- convert: one thread per compacted row --------------------
//   role 0 (A/outputs): [-2a_hi | -2a_lo | -2a_hi | sq_hi,sq_lo,1,1 | 0...]
//   role 1 (B/targets): [  b_hi |   b_hi |   b_lo | 1,1,sq_hi,sq_lo | 0...]
__global__ __launch_bounds__(256) void convert_kernel(
    const float* __restrict__ op, const float* __restrict__ tp) {
    int blk = blockIdx.y;              // (b, sel)
    int b   = blk >> 1;
    int sel = blk & 1;
    int p   = blockIdx.x * 256 + threadIdx.x;   // compacted row 0..2047

    int cntv = sel ? g_cntB[b] : g_cntA[b];
    int lim  = (cntv + 127) & ~127;
    if (lim > NPTS) lim = NPTS;
    if (p >= lim) return;

    const float* pts = sel ? tp : op;
    const int*   src = sel ? g_srcB : g_srcA;
    u32*        dstP = sel ? g_bfB : g_bfA;
    uint4* d16 = (uint4*)(dstP + ((size_t)b * NPTS + p) * 32);

    if (p >= cntv) {   // sentinel row
        __nv_bfloat16 big = __float2bfloat16(HUGEV);
        __nv_bfloat16 one = __float2bfloat16(1.0f);
        __nv_bfloat16 zer = __float2bfloat16(0.0f);
        u32 w24 = (sel == 0) ? pkbf(big, zer) : pkbf(one, one);
        u32 w25 = (sel == 0) ? pkbf(one, one) : pkbf(big, zer);
        uint4 z = make_uint4(0u, 0u, 0u, 0u);
        d16[0] = z; d16[1] = z; d16[2] = z; d16[3] = z; d16[4] = z; d16[5] = z;
        d16[6] = make_uint4(w24, w25, 0u, 0u);
        d16[7] = z;
        return;
    }

    const float4* s4 = (const float4*)(pts + ((size_t)b * NPTS + src[b * NPTS + p]) * DIM);
    float xv[16];
    #pragma unroll
    for (int q = 0; q < 4; q++) {
        float4 v = s4[q];
        xv[4*q+0] = v.x; xv[4*q+1] = v.y; xv[4*q+2] = v.z; xv[4*q+3] = v.w;
    }
    float sq = 0.0f;
    #pragma unroll
    for (int e = 0; e < 16; e++) sq += xv[e] * xv[e];

    __nv_bfloat16 h[16], l[16];
    #pragma unroll
    for (int e = 0; e < 16; e++) {
        __nv_bfloat16 hh = __float2bfloat16(xv[e]);
        float hf = __bfloat162float(hh);
        __nv_bfloat16 ll = __float2bfloat16(xv[e] - hf);
        if (sel == 0) {   // role 0: scale hi/lo by -2 (exact)
            hh = __float2bfloat16(-2.0f * hf);
            ll = __float2bfloat16(-2.0f * __bfloat162float(ll));
        }
        h[e] = hh; l[e] = ll;
    }
    __nv_bfloat16 sqh = __float2bfloat16(sq);
    __nv_bfloat16 sql = __float2bfloat16(sq - __bfloat162float(sqh));
    __nv_bfloat16 one = __float2bfloat16(1.0f);

    u32 H[8], L[8];
    #pragma unroll
    for (int j = 0; j < 8; j++) {
        H[j] = pkbf(h[2*j], h[2*j+1]);
        L[j] = pkbf(l[2*j], l[2*j+1]);
    }
    d16[0] = make_uint4(H[0], H[1], H[2], H[3]);
    d16[1] = make_uint4(H[4], H[5], H[6], H[7]);
    if (sel == 0) {
        d16[2] = make_uint4(L[0], L[1], L[2], L[3]);
        d16[3] = make_uint4(L[4], L[5], L[6], L[7]);
        d16[4] = make_uint4(H[0], H[1], H[2], H[3]);
        d16[5] = make_uint4(H[4], H[5], H[6], H[7]);
    } else {
        d16[2] = make_uint4(H[0], H[1], H[2], H[3]);
        d16[3] = make_uint4(H[4], H[5], H[6], H[7]);
        d16[4] = make_uint4(L[0], L[1], L[2], L[3]);
        d16[5] = make_uint4(L[4], L[5], L[6], L[7]);
    }
    u32 w24 = (sel == 0) ? pkbf(sqh, sql) : pkbf(one, one);
    u32 w25 = (sel == 0) ? pkbf(one, one) : pkbf(sqh, sql);
    d16[6] = make_uint4(w24, w25, 0u, 0u);
    d16[7] = make_uint4(0u, 0u, 0u, 0u);
}

// --------- pair kernel: mma.sync bf16 + fused finalize ---------------------
__global__ __launch_bounds__(256, 2) void mma_pair_kernel(float* out) {
    int b  = blockIdx.y;
    int Nv = g_cntA[b];
    int Mv = g_cntB[b];
    int active = (Nv + 127) >> 7;
    if (active < 1) active = 1;
    int bx = blockIdx.x;
    if (bx >= active) return;
    int n0 = bx * 128;

    __shared__ __align__(16) char Asm[128 * RSTR];
    __shared__ __align__(16) char Bsm[128 * RSTR];
    __shared__ float csh[4][128];
    __shared__ float rsh[2][128];
    __shared__ int   s_last;

    int tid  = threadIdx.x;
    int lane = tid & 31;
    int wid  = tid >> 5;
    int wrow = wid & 3;        // row group (32 rows)
    int cg   = wid >> 2;       // col half (64 cols)
    int gid  = lane >> 2;      // 0..7
    int tig  = lane & 3;       // 0..3

    if (n0 < Nv) {
        // ---- load A tile (128 rows x 128B), 2 threads per row ----
        {
            int row = tid >> 1, half = tid & 1;
            const uint4* s = (const uint4*)(g_bfA + ((size_t)b * NPTS + n0 + row) * 32) + half * 4;
            uint4* d = (uint4*)(Asm + row * RSTR + half * 64);
            d[0] = s[0]; d[1] = s[1]; d[2] = s[2]; d[3] = s[3];
        }

        float rmin[4] = {HUGEV, HUGEV, HUGEV, HUGEV};
        int mtiles = (Mv + 127) >> 7;

        const char* Aw = Asm + (wrow * 32 + gid) * RSTR + tig * 4;

        for (int mt = 0; mt < mtiles; mt++) {
            int m0 = mt * 128;
            {
                int row = tid >> 1, half = tid & 1;
                const uint4* s = (const uint4*)(g_bfB + ((size_t)b * NPTS + m0 + row) * 32) + half * 4;
                uint4* d = (uint4*)(Bsm + row * RSTR + half * 64);
                d[0] = s[0]; d[1] = s[1]; d[2] = s[2]; d[3] = s[3];
            }
            __syncthreads();

            float acc[2][8][4];
            #pragma unroll
            for (int mi = 0; mi < 2; mi++)
                #pragma unroll
                for (int nj = 0; nj < 8; nj++)
                    #pragma unroll
                    for (int q = 0; q < 4; q++) acc[mi][nj][q] = 0.0f;

            const char* Bw = Bsm + (cg * 64 + gid) * RSTR + tig * 4;
            #pragma unroll
            for (int ks = 0; ks < 4; ks++) {
                u32 a[2][4];
                #pragma unroll
                for (int mi = 0; mi < 2; mi++) {
                    const char* ab = Aw + mi * 16 * RSTR + ks * 32;
                    a[mi][0] = *(const u32*)(ab);
                    a[mi][1] = *(const u32*)(ab + 8 * RSTR);
                    a[mi][2] = *(const u32*)(ab + 16);
                    a[mi][3] = *(const u32*)(ab + 8 * RSTR + 16);
                }
                #pragma unroll
                for (int nj = 0; nj < 8; nj++) {
                    const char* bb = Bw + nj * 8 * RSTR + ks * 32;
                    u32 b0 = *(const u32*)(bb);
                    u32 b1 = *(const u32*)(bb + 16);
                    mma16816(acc[0][nj], a[0], b0, b1);
                    mma16816(acc[1][nj], a[1], b0, b1);
                }
            }

            // ---- epilogue: row/col mins ----
            #pragma unroll
            for (int nj = 0; nj < 8; nj++) {
                float cm0 = fminf(fminf(acc[0][nj][0], acc[0][nj][2]),
                                  fminf(acc[1][nj][0], acc[1][nj][2]));
                float cm1 = fminf(fminf(acc[0][nj][1], acc[0][nj][3]),
                                  fminf(acc[1][nj][1], acc[1][nj][3]));
                #pragma unroll
                for (int mi = 0; mi < 2; mi++) {
                    rmin[2*mi]   = fminf(rmin[2*mi],
                                         fminf(acc[mi][nj][0], acc[mi][nj][1]));
                    rmin[2*mi+1] = fminf(rmin[2*mi+1],
                                         fminf(acc[mi][nj][2], acc[mi][nj][3]));
                }
                cm0 = fmaxf(cm0, 0.0f);
                cm1 = fmaxf(cm1, 0.0f);
                #pragma unroll
                for (int d = 4; d < 32; d <<= 1) {
                    cm0 = fminf(cm0, __shfl_xor_sync(0xFFFFFFFFu, cm0, d));
                    cm1 = fminf(cm1, __shfl_xor_sync(0xFFFFFFFFu, cm1, d));
                }
                if (gid == 0) {
                    csh[wrow][cg * 64 + nj * 8 + tig * 2]     = cm0;
                    csh[wrow][cg * 64 + nj * 8 + tig * 2 + 1] = cm1;
                }
            }
            __syncthreads();
            if (tid < 128) {
                float v = fminf(fminf(csh[0][tid], csh[1][tid]),
                                fminf(csh[2][tid], csh[3][tid]));
                if (m0 + tid < Mv)
                    atomicMin(&g_colmin[b * NPTS + m0 + tid], __float_as_int(v));
            }
            __syncthreads();
        }

        // ---- row mins ----
        #pragma unroll
        for (int r = 0; r < 4; r++) {
            rmin[r] = fminf(rmin[r], __shfl_xor_sync(0xFFFFFFFFu, rmin[r], 1));
            rmin[r] = fminf(rmin[r], __shfl_xor_sync(0xFFFFFFFFu, rmin[r], 2));
        }
        if (tig == 0) {
            #pragma unroll
            for (int mi = 0; mi < 2; mi++) {
                rsh[cg][wrow * 32 + mi * 16 + gid]     = rmin[2*mi];
                rsh[cg][wrow * 32 + mi * 16 + gid + 8] = rmin[2*mi+1];
            }
        }
        __syncthreads();
        if (tid < 128)
            g_minA[b * NPTS + n0 + tid] =
                fmaxf(fminf(rsh[0][tid], rsh[1][tid]), 0.0f);
    }

    // ---- fused finalize: last arriving block sums both directions ----
    __threadfence();
    __syncthreads();
    if (tid == 0)
        s_last = (atomicAdd(&g_done[b], 1) == active - 1) ? 1 : 0;
    __syncthreads();
    if (s_last) {
        float s = 0.0f;
        for (int n = tid; n < Nv; n += 256) {
            float v = __ldcg(&g_minA[b * NPTS + n]);
            v = (v >= 1e29f) ? BIG2 : v;
            s += v * g_wA[b * NPTS + n];
        }
        for (int m = tid; m < Mv; m += 256) {
            float v = __int_as_float(__ldcg(&g_colmin[b * NPTS + m]));
            v = (v >= 1e29f) ? BIG2 : v;
            s += v * g_wB[b * NPTS + m];
        }
        #pragma unroll
        for (int d = 16; d > 0; d >>= 1)
            s += __shfl_xor_sync(0xFFFFFFFFu, s, d);
        __shared__ float wred[8];
        if (lane == 0) wred[wid] = s;
        __syncthreads();
        if (tid == 0) {
            float t = 0.0f;
            #pragma unroll
            for (int wI = 0; wI < 8; wI++) t += wred[wI];
            out[b] = t;
        }
    }
}

// ---------------- launch ----------------
extern "C" void kernel_launch(void* const* d_in, const int* in_sizes, int n_in,
                              void* d_out, int out_size) {
    const float* ow = (const float*)d_in[0];  // [B, N]
    const float* op = (const float*)d_in[1];  // [B, N, D]
    const float* tw = (const float*)d_in[2];  // [B, M]
    const float* tp = (const float*)d_in[3];  // [B, M, D]
    float* out = (float*)d_out;               // [B]

    scan_kernel<<<2 * BATCH, 1024>>>(ow, tw);
    dim3 cgrid(NPTS / 256, 2 * BATCH);
    convert_kernel<<<cgrid, 256>>>(op, tp);
    dim3 grid(NPTS / 128, BATCH);             // 16 row slots x 32 batches
    mma_pair_kernel<<<grid, 256>>>(out);
}